// round 6
// baseline (speedup 1.0000x reference)
#include <cuda_runtime.h>
#include <cuda_bf16.h>

#define NMAX 4096
#define BIGF 1e30f
#define TILE 128

// Scratch (__device__ globals; allocation is forbidden)
__device__ unsigned int g_d1[NMAX];   // min over m1 rows, per column j (float bits)
__device__ unsigned int g_d2[NMAX];   // min over m2 cols, per row i    (float bits)
__device__ unsigned int g_ctr = 0;    // last-block counter (self-resets via atomicInc wrap)

// ---------------------------------------------------------------------------
// Fused: inline prep + tiled masked-min (dot-product expansion) + last-block
// finalize. 128x128 tile / block, 256 threads (16x16), 8x8 micro-tile.
// D = rr + cc - 2*dot. u = dot + ci (ci=-0.5cc):
//   col candidate: fma(u,-2, rr+rp);  row candidate: fma(u,-2, cp) (+rr after)
// => 5 FFMA + 2 FMNMX per pair.
// ---------------------------------------------------------------------------
__global__ void __launch_bounds__(256) fused_kernel(const float* __restrict__ norm,
                                                    const float* __restrict__ pts,
                                                    float* __restrict__ out,
                                                    int n, int nblocks) {
    __shared__ float4 srow[TILE];         // hx, hy, hz, rr
    __shared__ float  srowA[TILE];        // rr + rowPenalty
    __shared__ float4 scol[TILE];         // cx, cy, cz, ci (= -0.5*cc)
    __shared__ float  scolP[TILE];        // colPenalty
    __shared__ unsigned int credu[TILE];
    __shared__ unsigned int rredu[TILE];
    __shared__ int slast;
    __shared__ float sred[4][8];

    int t = threadIdx.x;
    int i0 = blockIdx.y * TILE;
    int j0 = blockIdx.x * TILE;

    float nx = __ldg(norm), ny = __ldg(norm + 1), nz = __ldg(norm + 2), dd = __ldg(norm + 3);
    float nn = nx * nx + ny * ny + nz * nz;

    if (t < TILE) {                       // rows: reflected points
        int gi = i0 + t;
        float4 v = make_float4(0.f, 0.f, 0.f, 0.f);
        float A = BIGF;
        if (gi < n) {
            float px = pts[3 * gi], py = pts[3 * gi + 1], pz = pts[3 * gi + 2];
            float ts = -2.0f * (px * nx + py * ny + pz * nz + dd);
            float k = ts / nn;
            float hx = fmaf(k, nx, px), hy = fmaf(k, ny, py), hz = fmaf(k, nz, pz);
            float rr = fmaf(hx, hx, fmaf(hy, hy, hz * hz));
            v = make_float4(hx, hy, hz, rr);
            A = rr + (ts > 0.0f ? 0.0f : BIGF);
        }
        srow[t] = v;
        srowA[t] = A;
        credu[t] = __float_as_uint(BIGF);
    } else {                              // cols: original points
        int u = t - TILE;
        int gj = j0 + u;
        float4 v = make_float4(0.f, 0.f, 0.f, 0.f);
        float P = BIGF;
        if (gj < n) {
            float px = pts[3 * gj], py = pts[3 * gj + 1], pz = pts[3 * gj + 2];
            float ts = -2.0f * (px * nx + py * ny + pz * nz + dd);
            float cc = fmaf(px, px, fmaf(py, py, pz * pz));
            v = make_float4(px, py, pz, -0.5f * cc);
            P = (ts > 0.0f ? BIGF : 0.0f);
        }
        scol[u] = v;
        scolP[u] = P;
        rredu[u] = __float_as_uint(BIGF);
    }
    __syncthreads();

    int tx = t & 15, ty = t >> 4;

    float RX[8], RY[8], RZ[8], RA[8], RR[8];
#pragma unroll
    for (int r = 0; r < 8; r++) {
        float4 v = srow[ty * 8 + r];
        RX[r] = v.x; RY[r] = v.y; RZ[r] = v.z; RR[r] = v.w;
        RA[r] = srowA[ty * 8 + r];
    }
    float CX[8], CY[8], CZ[8], CI[8], CP[8];
#pragma unroll
    for (int c = 0; c < 8; c++) {
        float4 v = scol[c * 16 + tx];     // consecutive tx -> conflict-free
        CX[c] = v.x; CY[c] = v.y; CZ[c] = v.z; CI[c] = v.w;
        CP[c] = scolP[c * 16 + tx];
    }

    float cmin[8], rmin[8];
#pragma unroll
    for (int k = 0; k < 8; k++) { cmin[k] = BIGF; rmin[k] = BIGF; }

#pragma unroll
    for (int r = 0; r < 8; r++) {
        float rxv = RX[r], ryv = RY[r], rzv = RZ[r], Av = RA[r];
        float rm = rmin[r];
#pragma unroll
        for (int c = 0; c < 8; c++) {
            float u = fmaf(rzv, CZ[c], fmaf(ryv, CY[c], fmaf(rxv, CX[c], CI[c])));
            cmin[c] = fminf(cmin[c], fmaf(u, -2.0f, Av));
            rm      = fminf(rm,      fmaf(u, -2.0f, CP[c]));
        }
        rmin[r] = rm;
    }

    // block-local combine (clamp: cancellation can give ~-1e-6; keeps uint order valid)
#pragma unroll
    for (int c = 0; c < 8; c++)
        atomicMin(&credu[c * 16 + tx], __float_as_uint(fmaxf(cmin[c], 0.0f)));
#pragma unroll
    for (int r = 0; r < 8; r++) {
        float v = fmaxf(rmin[r] + RR[r], 0.0f);
        atomicMin(&rredu[ty * 8 + r], __float_as_uint(v));
    }
    __syncthreads();

    if (t < TILE) {
        int gj = j0 + t;
        if (gj < n) atomicMin(&g_d1[gj], credu[t]);
    } else {
        int u = t - TILE;
        int gi = i0 + u;
        if (gi < n) atomicMin(&g_d2[gi], rredu[u]);
    }

    // ---- last-block finalize (single fence by one thread) ----
    __syncthreads();
    if (t == 0) {
        __threadfence();
        slast = (atomicInc(&g_ctr, (unsigned int)(nblocks - 1)) ==
                 (unsigned int)(nblocks - 1));
    }
    __syncthreads();
    if (!slast) return;

    float s1 = 0.f, s2 = 0.f, c1 = 0.f, c2 = 0.f;
#pragma unroll 4
    for (int i = t; i < n; i += 256) {
        float px = pts[3 * i], py = pts[3 * i + 1], pz = pts[3 * i + 2];
        float ts = -2.0f * (px * nx + py * ny + pz * nz + dd);
        float d1v = __uint_as_float(g_d1[i]);
        float d2v = __uint_as_float(g_d2[i]);
        if (ts > 0.0f) { s2 += d2v; c1 += 1.0f; }   // m1 rows -> av2 terms
        else           { s1 += d1v; c2 += 1.0f; }   // m2 cols -> av1 terms
    }
#pragma unroll
    for (int o = 16; o > 0; o >>= 1) {
        s1 += __shfl_xor_sync(0xffffffffu, s1, o);
        s2 += __shfl_xor_sync(0xffffffffu, s2, o);
        c1 += __shfl_xor_sync(0xffffffffu, c1, o);
        c2 += __shfl_xor_sync(0xffffffffu, c2, o);
    }
    int w = t >> 5, l = t & 31;
    if (l == 0) { sred[0][w] = s1; sred[1][w] = s2; sred[2][w] = c1; sred[3][w] = c2; }
    __syncthreads();
    if (t == 0) {
        float S1 = 0.f, S2 = 0.f, C1 = 0.f, C2 = 0.f;
#pragma unroll
        for (int i = 0; i < 8; i++) {
            S1 += sred[0][i]; S2 += sred[1][i]; C1 += sred[2][i]; C2 += sred[3][i];
        }
        C1 = fmaxf(C1, 1.0f);
        C2 = fmaxf(C2, 1.0f);
        out[0] = (0.5f * (S1 / C2) + 0.5f * (S2 / C1)) * 100.0f;
    }
}

// ---------------------------------------------------------------------------
extern "C" void kernel_launch(void* const* d_in, const int* in_sizes, int n_in,
                              void* d_out, int out_size) {
    const float* a0 = (const float*)d_in[0];
    const float* a1 = (const float*)d_in[1];
    const float* norm;
    const float* pts;
    int n;
    if (in_sizes[0] == 4) { norm = a0; pts = a1; n = in_sizes[1] / 3; }
    else                  { norm = a1; pts = a0; n = in_sizes[0] / 3; }

    float* out = (float*)d_out;

    // init min arrays to "+inf" (0x7F7F7F7F = 3.39e38 > any candidate)
    void* p1 = nullptr; void* p2 = nullptr;
    cudaGetSymbolAddress(&p1, g_d1);
    cudaGetSymbolAddress(&p2, g_d2);
    cudaMemsetAsync(p1, 0x7F, (size_t)n * sizeof(unsigned int), 0);
    cudaMemsetAsync(p2, 0x7F, (size_t)n * sizeof(unsigned int), 0);

    int nt = (n + TILE - 1) / TILE;
    dim3 grid(nt, nt);
    fused_kernel<<<grid, 256>>>(norm, pts, out, n, nt * nt);
}

// round 7
// speedup vs baseline: 1.0790x; 1.0790x over previous
#include <cuda_runtime.h>
#include <cuda_bf16.h>

#define NMAX 4096
#define BIGF 1e30f
#define TILE 128

// Scratch (__device__ globals; allocation is forbidden)
__device__ unsigned int g_d1[NMAX];   // min over m1 rows, per column j (float bits)
__device__ unsigned int g_d2[NMAX];   // min over m2 cols, per row i    (float bits)

// ---------------------------------------------------------------------------
// Dist kernel: inline prep + tiled masked-min with dot-product expansion.
// 128x128 tile / block, 256 threads (16x16), 8x8 register micro-tile.
// D = rr + cc - 2*dot. u = dot + ci (ci=-0.5cc):
//   col candidate: fma(u,-2, rr+rp);  row candidate: fma(u,-2, cp) (+rr after)
// Row mins reduced via half-warp shuffles (each row's 16 tx-owners are lanes
// (ty&1)*16 + 0..15 of one warp) -> direct global atomicMin, no smem atomics.
// Col mins: shfl_xor(16) pairs the warp's two ty, then 8 conflict-free smem
// atomics from lanes<16 only.
// ---------------------------------------------------------------------------
__global__ void __launch_bounds__(256) dist_kernel(const float* __restrict__ norm,
                                                   const float* __restrict__ pts,
                                                   int n) {
    __shared__ float4 srow[TILE];         // hx, hy, hz, rr
    __shared__ float  srowA[TILE];        // rr + rowPenalty
    __shared__ float4 scol[TILE];         // cx, cy, cz, ci (= -0.5*cc)
    __shared__ float  scolP[TILE];        // colPenalty
    __shared__ unsigned int credu[TILE];

    int t = threadIdx.x;
    int i0 = blockIdx.y * TILE;
    int j0 = blockIdx.x * TILE;

    float nx = __ldg(norm), ny = __ldg(norm + 1), nz = __ldg(norm + 2), dd = __ldg(norm + 3);
    float nn = nx * nx + ny * ny + nz * nz;

    if (t < TILE) {                       // rows: reflected points
        int gi = i0 + t;
        float4 v = make_float4(0.f, 0.f, 0.f, 0.f);
        float A = BIGF;
        if (gi < n) {
            float px = pts[3 * gi], py = pts[3 * gi + 1], pz = pts[3 * gi + 2];
            float ts = -2.0f * (px * nx + py * ny + pz * nz + dd);
            float k = ts / nn;
            float hx = fmaf(k, nx, px), hy = fmaf(k, ny, py), hz = fmaf(k, nz, pz);
            float rr = fmaf(hx, hx, fmaf(hy, hy, hz * hz));
            v = make_float4(hx, hy, hz, rr);
            A = rr + (ts > 0.0f ? 0.0f : BIGF);
        }
        srow[t] = v;
        srowA[t] = A;
        credu[t] = __float_as_uint(BIGF);
    } else {                              // cols: original points
        int u = t - TILE;
        int gj = j0 + u;
        float4 v = make_float4(0.f, 0.f, 0.f, 0.f);
        float P = BIGF;
        if (gj < n) {
            float px = pts[3 * gj], py = pts[3 * gj + 1], pz = pts[3 * gj + 2];
            float ts = -2.0f * (px * nx + py * ny + pz * nz + dd);
            float cc = fmaf(px, px, fmaf(py, py, pz * pz));
            v = make_float4(px, py, pz, -0.5f * cc);
            P = (ts > 0.0f ? BIGF : 0.0f);
        }
        scol[u] = v;
        scolP[u] = P;
    }
    __syncthreads();

    int tx = t & 15, ty = t >> 4;

    float RX[8], RY[8], RZ[8], RA[8], RR[8];
#pragma unroll
    for (int r = 0; r < 8; r++) {
        float4 v = srow[ty * 8 + r];
        RX[r] = v.x; RY[r] = v.y; RZ[r] = v.z; RR[r] = v.w;
        RA[r] = srowA[ty * 8 + r];
    }
    float CX[8], CY[8], CZ[8], CI[8], CP[8];
#pragma unroll
    for (int c = 0; c < 8; c++) {
        float4 v = scol[c * 16 + tx];     // consecutive tx -> conflict-free
        CX[c] = v.x; CY[c] = v.y; CZ[c] = v.z; CI[c] = v.w;
        CP[c] = scolP[c * 16 + tx];
    }

    float cmin[8], rmin[8];
#pragma unroll
    for (int k = 0; k < 8; k++) { cmin[k] = BIGF; rmin[k] = BIGF; }

#pragma unroll
    for (int r = 0; r < 8; r++) {
        float rxv = RX[r], ryv = RY[r], rzv = RZ[r], Av = RA[r];
        float rm = rmin[r];
#pragma unroll
        for (int c = 0; c < 8; c++) {
            float u = fmaf(rzv, CZ[c], fmaf(ryv, CY[c], fmaf(rxv, CX[c], CI[c])));
            cmin[c] = fminf(cmin[c], fmaf(u, -2.0f, Av));
            rm      = fminf(rm,      fmaf(u, -2.0f, CP[c]));
        }
        rmin[r] = rm;
    }

    // ---- row mins: half-warp shuffle reduce over the 16 tx-owners ----
#pragma unroll
    for (int r = 0; r < 8; r++) {
        float v = rmin[r];
#pragma unroll
        for (int o = 8; o > 0; o >>= 1)
            v = fminf(v, __shfl_xor_sync(0xffffffffu, v, o));
        if (tx == 0) {
            int gi = i0 + ty * 8 + r;
            if (gi < n)
                atomicMin(&g_d2[gi], __float_as_uint(fmaxf(v + RR[r], 0.0f)));
        }
    }

    // ---- col mins: pair the warp's two ty via shfl, then conflict-free atomics ----
#pragma unroll
    for (int c = 0; c < 8; c++) {
        float v = fminf(cmin[c], __shfl_xor_sync(0xffffffffu, cmin[c], 16));
        if ((t & 31) < 16)
            atomicMin(&credu[c * 16 + tx], __float_as_uint(fmaxf(v, 0.0f)));
    }
    __syncthreads();

    if (t < TILE) {
        int gj = j0 + t;
        if (gj < n) atomicMin(&g_d1[gj], credu[t]);
    }
}

// ---------------------------------------------------------------------------
// Final masked means + scalar output. 1024 threads, 4 unrolled independent
// iterations per thread (MLP ~20) instead of a serialized latency chain.
// ---------------------------------------------------------------------------
__global__ void __launch_bounds__(1024) reduce_kernel(const float* __restrict__ norm,
                                                      const float* __restrict__ pts,
                                                      float* __restrict__ out, int n) {
    int t = threadIdx.x;
    float nx = __ldg(norm), ny = __ldg(norm + 1), nz = __ldg(norm + 2), dd = __ldg(norm + 3);
    float s1 = 0.f, s2 = 0.f, c1 = 0.f, c2 = 0.f;
#pragma unroll 4
    for (int i = t; i < n; i += 1024) {
        float px = __ldg(pts + 3 * i), py = __ldg(pts + 3 * i + 1), pz = __ldg(pts + 3 * i + 2);
        float d1v = __uint_as_float(g_d1[i]);
        float d2v = __uint_as_float(g_d2[i]);
        float ts = -2.0f * (px * nx + py * ny + pz * nz + dd);
        if (ts > 0.0f) { s2 += d2v; c1 += 1.0f; }   // m1 rows -> av2 terms
        else           { s1 += d1v; c2 += 1.0f; }   // m2 cols -> av1 terms
    }
#pragma unroll
    for (int o = 16; o > 0; o >>= 1) {
        s1 += __shfl_xor_sync(0xffffffffu, s1, o);
        s2 += __shfl_xor_sync(0xffffffffu, s2, o);
        c1 += __shfl_xor_sync(0xffffffffu, c1, o);
        c2 += __shfl_xor_sync(0xffffffffu, c2, o);
    }
    __shared__ float sh[4][32];
    int w = t >> 5, l = t & 31;
    if (l == 0) { sh[0][w] = s1; sh[1][w] = s2; sh[2][w] = c1; sh[3][w] = c2; }
    __syncthreads();
    if (w == 0) {
        float a = sh[0][l], b = sh[1][l], c = sh[2][l], d = sh[3][l];
#pragma unroll
        for (int o = 16; o > 0; o >>= 1) {
            a += __shfl_xor_sync(0xffffffffu, a, o);
            b += __shfl_xor_sync(0xffffffffu, b, o);
            c += __shfl_xor_sync(0xffffffffu, c, o);
            d += __shfl_xor_sync(0xffffffffu, d, o);
        }
        if (l == 0) {
            c = fmaxf(c, 1.0f);   // C1
            d = fmaxf(d, 1.0f);   // C2
            out[0] = (0.5f * (a / d) + 0.5f * (b / c)) * 100.0f;
        }
    }
}

// ---------------------------------------------------------------------------
extern "C" void kernel_launch(void* const* d_in, const int* in_sizes, int n_in,
                              void* d_out, int out_size) {
    const float* a0 = (const float*)d_in[0];
    const float* a1 = (const float*)d_in[1];
    const float* norm;
    const float* pts;
    int n;
    if (in_sizes[0] == 4) { norm = a0; pts = a1; n = in_sizes[1] / 3; }
    else                  { norm = a1; pts = a0; n = in_sizes[0] / 3; }

    float* out = (float*)d_out;

    // init min arrays to "+inf" (0x7F7F7F7F = 3.39e38 > any candidate)
    void* p1 = nullptr; void* p2 = nullptr;
    cudaGetSymbolAddress(&p1, g_d1);
    cudaGetSymbolAddress(&p2, g_d2);
    cudaMemsetAsync(p1, 0x7F, (size_t)n * sizeof(unsigned int), 0);
    cudaMemsetAsync(p2, 0x7F, (size_t)n * sizeof(unsigned int), 0);

    int nt = (n + TILE - 1) / TILE;
    dim3 grid(nt, nt);
    dist_kernel<<<grid, 256>>>(norm, pts, n);

    reduce_kernel<<<1, 1024>>>(norm, pts, out, n);
}